// round 7
// baseline (speedup 1.0000x reference)
#include <cuda_runtime.h>
#include <cuda_fp16.h>
#include <math.h>

#define N_NODES 100000
#define N_EDGES 1000000
#define KD 128
#define VD 64
#define NBLK 391   // ceil(N_NODES / 256)

// ---------------- scratch (static device allocations, graph-safe) ----------
__device__ __align__(16) int4   g_packed[N_EDGES];   // {h, a, v, bitcast(score)}
__device__ __align__(16) int4   g_csr[N_EDGES];      // CSR-ordered copies
__device__ __align__(16) __half g_attP[N_NODES * KD];  // att_feats @ W[0:128]
__device__ __align__(16) __half g_valP[N_NODES * KD];  // val_feats @ W[128:192]
__device__ float g_rowsum[N_NODES];
__device__ float g_sent[N_NODES];
__device__ float g_satt[N_NODES];
__device__ int   g_deg[N_NODES];
__device__ int   g_off[N_NODES];
__device__ int   g_cursor[N_NODES];
__device__ int   g_bsum[NBLK];
__device__ int   g_boff[NBLK];
__device__ int   g_idx64;

// ---------------- dtype sniff: int64 vs int32 triples (parallel) -----------
__global__ void sniff_kernel(const int* tri32) {
    int t = threadIdx.x;
    int bad = (tri32[2 * t + 1] != 0) ? 1 : 0;
    int any = __syncthreads_or(bad);
    if (t == 0) g_idx64 = any ? 0 : 1;
}

// ------- per-node score pre-reduction + counter resets ----------------------
__global__ void score_pre_kernel(const float* __restrict__ ent,
                                 const float* __restrict__ att,
                                 const float* __restrict__ aw) {
    int warp = (blockIdx.x * blockDim.x + threadIdx.x) >> 5;
    int lane = threadIdx.x & 31;
    if (warp >= N_NODES) return;

    const float4* ent4 = reinterpret_cast<const float4*>(ent);
    const float4* att4 = reinterpret_cast<const float4*>(att);
    const float4* aw4  = reinterpret_cast<const float4*>(aw);

    float4 e = ent4[warp * 32 + lane];
    float4 a = att4[warp * 32 + lane];
    float4 we = __ldg(&aw4[lane]);
    float4 wa = __ldg(&aw4[32 + lane]);

    float se = e.x * we.x + e.y * we.y + e.z * we.z + e.w * we.w;
    float sa = a.x * wa.x + a.y * wa.y + a.z * wa.z + a.w * wa.w;
    #pragma unroll
    for (int o = 16; o; o >>= 1) {
        se += __shfl_xor_sync(0xFFFFFFFFu, se, o);
        sa += __shfl_xor_sync(0xFFFFFFFFu, sa, o);
    }
    if (lane == 0) {
        g_sent[warp] = se;
        g_satt[warp] = sa;
        g_rowsum[warp] = 0.f;
        g_deg[warp] = 0;
    }
}

// ---------------- projection GEMM: dst[r][c] = sum_j src[r][j] W[woff+j][c] --
// 256 threads, 8 warps, 4 rows/warp -> 32 rows/block, grid = 3125 (exact).
// Wt transposed in smem, stride K+4 (== 4 mod 32 -> conflict-free LDS.128).
// f32x2 over j-pairs: both FFMA2 operands are halves of 128-bit loads (no MOVs).
__device__ __forceinline__ void ffma2(unsigned long long& d,
                                      unsigned long long a,
                                      unsigned long long b) {
    asm("fma.rn.f32x2 %0, %1, %2, %0;" : "+l"(d) : "l"(a), "l"(b));
}
__device__ __forceinline__ void unpack2(unsigned long long p, float& x, float& y) {
    asm("mov.b64 {%0, %1}, %2;" : "=f"(x), "=f"(y) : "l"(p));
}

__global__ void __launch_bounds__(256, 2)
proj_kernel(const float* __restrict__ src, const float* __restrict__ W,
            __half* __restrict__ dst, int K, int woff) {
    extern __shared__ float Wt[];          // [128][K+4]
    int stride = K + 4;
    int tid  = threadIdx.x;
    int wid  = tid >> 5;
    int lane = tid & 31;

    for (int idx = tid; idx < K * KD; idx += 256) {
        int j = idx >> 7;          // 0..K-1
        int c = idx & 127;         // 0..127
        Wt[c * stride + j] = W[(woff + j) * KD + c];
    }
    __syncthreads();

    int row0 = (blockIdx.x * 8 + wid) * 4;      // exact: 3125*32 = 100000

    unsigned long long acc[4][4];               // [c][r], (even-j, odd-j)
    #pragma unroll
    for (int c = 0; c < 4; c++)
        #pragma unroll
        for (int r = 0; r < 4; r++) acc[c][r] = 0ull;

    #pragma unroll 1
    for (int j = 0; j < K; j += 4) {
        ulonglong2 a[4];
        #pragma unroll
        for (int r = 0; r < 4; r++)
            a[r] = __ldg(reinterpret_cast<const ulonglong2*>(
                src + (row0 + r) * K + j));
        #pragma unroll
        for (int c = 0; c < 4; c++) {
            ulonglong2 wt = *reinterpret_cast<const ulonglong2*>(
                Wt + (lane + 32 * c) * stride + j);
            #pragma unroll
            for (int r = 0; r < 4; r++) {
                ffma2(acc[c][r], a[r].x, wt.x);
                ffma2(acc[c][r], a[r].y, wt.y);
            }
        }
    }

    #pragma unroll
    for (int r = 0; r < 4; r++) {
        #pragma unroll
        for (int c = 0; c < 4; c++) {
            float lo, hi;
            unpack2(acc[c][r], lo, hi);
            dst[(row0 + r) * KD + lane + 32 * c] = __float2half_rn(lo + hi);
        }
    }
}

// ---------------- pass A: per-edge score + degree histogram -----------------
__global__ void score_edge_kernel(const void* __restrict__ tri,
                                  const float* __restrict__ ab) {
    int e = blockIdx.x * blockDim.x + threadIdx.x;
    if (e >= N_EDGES) return;
    int h, a, v;
    if (g_idx64) {
        const long long* t = reinterpret_cast<const long long*>(tri) + 3LL * e;
        h = (int)t[0]; a = (int)t[1]; v = (int)t[2];
    } else {
        const int* t = reinterpret_cast<const int*>(tri) + 3 * e;
        h = t[0]; a = t[1]; v = t[2];
    }
    float s = g_sent[h] + g_satt[a] + __ldg(&ab[0]);
    s = s > 0.f ? s : 0.2f * s;                 // leaky_relu(0.2)
    float sc = __expf(s);
    atomicAdd(&g_rowsum[h], sc);
    atomicAdd(&g_deg[h], 1);
    g_packed[e] = make_int4(h, a, v, __float_as_int(sc));
}

// ---------------- 3-phase exclusive scan over degrees -----------------------
__global__ void scan_a_kernel() {
    __shared__ int sh[256];
    int t = threadIdx.x, b = blockIdx.x;
    int node = b * 256 + t;
    sh[t] = (node < N_NODES) ? g_deg[node] : 0;
    __syncthreads();
    #pragma unroll
    for (int d = 128; d; d >>= 1) {
        if (t < d) sh[t] += sh[t + d];
        __syncthreads();
    }
    if (t == 0) g_bsum[b] = sh[0];
}

__global__ void scan_b_kernel() {
    __shared__ int sh[512];
    int t = threadIdx.x;
    int v = (t < NBLK) ? g_bsum[t] : 0;
    sh[t] = v;
    __syncthreads();
    #pragma unroll
    for (int d = 1; d < 512; d <<= 1) {
        int x = (t >= d) ? sh[t - d] : 0;
        __syncthreads();
        sh[t] += x;
        __syncthreads();
    }
    if (t < NBLK) g_boff[t] = sh[t] - v;   // exclusive
}

__global__ void scan_c_kernel() {
    __shared__ int sh[256];
    int t = threadIdx.x, b = blockIdx.x;
    int node = b * 256 + t;
    int v = (node < N_NODES) ? g_deg[node] : 0;
    sh[t] = v;
    __syncthreads();
    #pragma unroll
    for (int d = 1; d < 256; d <<= 1) {
        int x = (t >= d) ? sh[t - d] : 0;
        __syncthreads();
        sh[t] += x;
        __syncthreads();
    }
    if (node < N_NODES) {
        int off = g_boff[b] + sh[t] - v;
        g_off[node] = off;
        g_cursor[node] = off;
    }
}

// ---------------- pass B: permute records into CSR order --------------------
__global__ void fill_kernel() {
    int e = blockIdx.x * blockDim.x + threadIdx.x;
    if (e >= N_EDGES) return;
    int4 p = g_packed[e];
    int pos = atomicAdd(&g_cursor[p.x], 1);
    g_csr[pos] = p;
}

// ------- pass C: aggregation in projected space + fused epilogue ------------
// warp per node; lane owns output cols 4*lane..4*lane+3.
// acc += score * (attP[a] + valP[v]); out = elu(acc/rowsum + ent).
__device__ __forceinline__ void acc_edge(uint2 ua, uint2 uv, float s,
                                         float4& acc) {
    __half2 p0 = __hadd2(*reinterpret_cast<__half2*>(&ua.x),
                         *reinterpret_cast<__half2*>(&uv.x));
    __half2 p1 = __hadd2(*reinterpret_cast<__half2*>(&ua.y),
                         *reinterpret_cast<__half2*>(&uv.y));
    float2 f0 = __half22float2(p0);
    float2 f1 = __half22float2(p1);
    acc.x += f0.x * s; acc.y += f0.y * s;
    acc.z += f1.x * s; acc.w += f1.y * s;
}

__global__ void aggregate_kernel(const float* __restrict__ ent,
                                 float* __restrict__ out) {
    int warp = (blockIdx.x * blockDim.x + threadIdx.x) >> 5;
    int lane = threadIdx.x & 31;
    if (warp >= N_NODES) return;
    int beg = g_off[warp];
    int deg = g_deg[warp];

    float4 acc = make_float4(0.f, 0.f, 0.f, 0.f);

    for (int base = 0; base < deg; base += 32) {
        int4 r = make_int4(0, 0, 0, 0);
        if (base + lane < deg) r = g_csr[beg + base + lane];
        int m = min(32, deg - base);
        int i = 0;
        for (; i + 4 <= m; i += 4) {
            uint2 UA[4], UV[4];
            float S[4];
            #pragma unroll
            for (int u = 0; u < 4; u++) {
                int a = __shfl_sync(0xFFFFFFFFu, r.y, i + u);
                int v = __shfl_sync(0xFFFFFFFFu, r.z, i + u);
                S[u]  = __int_as_float(__shfl_sync(0xFFFFFFFFu, r.w, i + u));
                UA[u] = *reinterpret_cast<const uint2*>(g_attP + a * KD + lane * 4);
                UV[u] = *reinterpret_cast<const uint2*>(g_valP + v * KD + lane * 4);
            }
            #pragma unroll
            for (int u = 0; u < 4; u++)
                acc_edge(UA[u], UV[u], S[u], acc);
        }
        for (; i < m; i++) {
            int a = __shfl_sync(0xFFFFFFFFu, r.y, i);
            int v = __shfl_sync(0xFFFFFFFFu, r.z, i);
            float s = __int_as_float(__shfl_sync(0xFFFFFFFFu, r.w, i));
            uint2 ua = *reinterpret_cast<const uint2*>(g_attP + a * KD + lane * 4);
            uint2 uv = *reinterpret_cast<const uint2*>(g_valP + v * KD + lane * 4);
            acc_edge(ua, uv, s, acc);
        }
    }

    float rs = g_rowsum[warp];
    float inv = rs > 0.f ? 1.f / rs : 0.f;
    float4 e = reinterpret_cast<const float4*>(ent)[warp * 32 + lane];
    float t0 = acc.x * inv + e.x;
    float t1 = acc.y * inv + e.y;
    float t2 = acc.z * inv + e.z;
    float t3 = acc.w * inv + e.w;
    float4 o;
    o.x = t0 > 0.f ? t0 : expm1f(t0);   // elu, alpha=1
    o.y = t1 > 0.f ? t1 : expm1f(t1);
    o.z = t2 > 0.f ? t2 : expm1f(t2);
    o.w = t3 > 0.f ? t3 : expm1f(t3);
    reinterpret_cast<float4*>(out)[warp * 32 + lane] = o;
}

// ---------------- launch ----------------------------------------------------
extern "C" void kernel_launch(void* const* d_in, const int* in_sizes, int n_in,
                              void* d_out, int out_size) {
    const void*  triples = d_in[0];                       // [1e6, 3] int64/int32
    const float* ent     = (const float*)d_in[1];         // [1e5, 128]
    const float* attf    = (const float*)d_in[2];         // [1e5, 128]
    const float* valf    = (const float*)d_in[3];         // [1e5, 64]
    const float* aw      = (const float*)d_in[4];         // [256]
    const float* ab      = (const float*)d_in[5];         // [1]
    const float* W       = (const float*)d_in[6];         // [192, 128]
    float* out           = (float*)d_out;                 // [1e5, 128]

    static bool attr_set = false;
    size_t proj_smem = (size_t)(KD * (KD + 4)) * sizeof(float);   // 67584
    if (!attr_set) {
        cudaFuncSetAttribute(proj_kernel, cudaFuncAttributeMaxDynamicSharedMemorySize,
                             (int)proj_smem);
        attr_set = true;
    }

    __half* attP; cudaGetSymbolAddress((void**)&attP, g_attP);
    __half* valP; cudaGetSymbolAddress((void**)&valP, g_valP);

    sniff_kernel<<<1, 256>>>((const int*)triples);
    score_pre_kernel<<<(N_NODES + 7) / 8, 256>>>(ent, attf, aw);
    proj_kernel<<<N_NODES / 32, 256, (size_t)(VD + 4) * KD * sizeof(float)>>>(
        valf, W, valP, VD, KD);                 // valP = val @ W[128:192]
    proj_kernel<<<N_NODES / 32, 256, proj_smem>>>(
        attf, W, attP, KD, 0);                  // attP = att @ W[0:128]
    score_edge_kernel<<<(N_EDGES + 255) / 256, 256>>>(triples, ab);
    scan_a_kernel<<<NBLK, 256>>>();
    scan_b_kernel<<<1, 512>>>();
    scan_c_kernel<<<NBLK, 256>>>();
    fill_kernel<<<(N_EDGES + 255) / 256, 256>>>();
    aggregate_kernel<<<(N_NODES * 32 + 255) / 256, 256>>>(ent, out);
}

// round 9
// speedup vs baseline: 1.0419x; 1.0419x over previous
#include <cuda_runtime.h>
#include <cuda_fp16.h>
#include <mma.h>
#include <math.h>
#include <cstdint>

using namespace nvcuda;

#define N_NODES 100000
#define N_EDGES 1000000
#define KD 128
#define VD 64
#define AGGD 192   // KD + VD
#define NBLK 391   // ceil(N_NODES / 256)
#define N_TILES 782  // ceil(N_NODES / 128)

// ---------------- scratch (static device allocations, graph-safe) ----------
__device__ __align__(16) int4   g_packed[N_EDGES];   // {h, a, v, bitcast(score)}
__device__ __align__(16) int4   g_csr[N_EDGES];      // CSR-ordered copies
__device__ __align__(16) __half g_attH[N_NODES * KD];
__device__ __align__(16) __half g_valH[N_NODES * VD];
__device__ __align__(16) __half g_aggH[N_NODES * AGGD];  // fp16 aggregated rows
__device__ __align__(16) __half g_Wt[KD * AGGD];         // Wt[n][k] = W[k][n]
__device__ float g_rowsum[N_NODES];
__device__ float g_sent[N_NODES];
__device__ float g_satt[N_NODES];
__device__ int   g_deg[N_NODES];
__device__ int   g_off[N_NODES];
__device__ int   g_cursor[N_NODES];
__device__ int   g_bsum[NBLK];
__device__ int   g_boff[NBLK];
__device__ int   g_idx64;

// ---------------- dtype sniff: int64 vs int32 triples (parallel) -----------
__global__ void sniff_kernel(const int* tri32) {
    int t = threadIdx.x;
    int bad = (tri32[2 * t + 1] != 0) ? 1 : 0;
    int any = __syncthreads_or(bad);
    if (t == 0) g_idx64 = any ? 0 : 1;
}

// ------- per-node score pre-reduction + att fp16 conversion + resets --------
__global__ void score_pre_kernel(const float* __restrict__ ent,
                                 const float* __restrict__ att,
                                 const float* __restrict__ aw) {
    int warp = (blockIdx.x * blockDim.x + threadIdx.x) >> 5;
    int lane = threadIdx.x & 31;
    if (warp >= N_NODES) return;

    const float4* ent4 = reinterpret_cast<const float4*>(ent);
    const float4* att4 = reinterpret_cast<const float4*>(att);
    const float4* aw4  = reinterpret_cast<const float4*>(aw);

    float4 e = ent4[warp * 32 + lane];
    float4 a = att4[warp * 32 + lane];
    float4 we = __ldg(&aw4[lane]);
    float4 wa = __ldg(&aw4[32 + lane]);

    __half2 h0 = __floats2half2_rn(a.x, a.y);
    __half2 h1 = __floats2half2_rn(a.z, a.w);
    uint2 packed;
    packed.x = *reinterpret_cast<unsigned*>(&h0);
    packed.y = *reinterpret_cast<unsigned*>(&h1);
    *reinterpret_cast<uint2*>(g_attH + warp * KD + lane * 4) = packed;

    float se = e.x * we.x + e.y * we.y + e.z * we.z + e.w * we.w;
    float sa = a.x * wa.x + a.y * wa.y + a.z * wa.z + a.w * wa.w;
    #pragma unroll
    for (int o = 16; o; o >>= 1) {
        se += __shfl_xor_sync(0xFFFFFFFFu, se, o);
        sa += __shfl_xor_sync(0xFFFFFFFFu, sa, o);
    }
    if (lane == 0) {
        g_sent[warp] = se;
        g_satt[warp] = sa;
        g_rowsum[warp] = 0.f;
        g_deg[warp] = 0;
    }
}

// ---------------- val fp16 conversion ---------------------------------------
__global__ void valconv_kernel(const float* __restrict__ valf) {
    int i = blockIdx.x * blockDim.x + threadIdx.x;
    int n4 = N_NODES * VD / 4;
    if (i >= n4) return;
    float4 v = reinterpret_cast<const float4*>(valf)[i];
    __half2 h0 = __floats2half2_rn(v.x, v.y);
    __half2 h1 = __floats2half2_rn(v.z, v.w);
    uint2 packed;
    packed.x = *reinterpret_cast<unsigned*>(&h0);
    packed.y = *reinterpret_cast<unsigned*>(&h1);
    *reinterpret_cast<uint2*>(g_valH + i * 4) = packed;
}

// ---------------- prepack W^T as fp16: Wt[n][k] = W[k][n] -------------------
__global__ void prepack_kernel(const float* __restrict__ W) {
    int idx = blockIdx.x * blockDim.x + threadIdx.x;
    if (idx >= KD * AGGD) return;
    int n = idx / AGGD;        // 0..127
    int k = idx % AGGD;        // 0..191
    g_Wt[idx] = __float2half_rn(W[k * KD + n]);
}

// ---------------- pass A: per-edge score + degree histogram -----------------
__global__ void score_edge_kernel(const void* __restrict__ tri,
                                  const float* __restrict__ ab) {
    int e = blockIdx.x * blockDim.x + threadIdx.x;
    if (e >= N_EDGES) return;
    int h, a, v;
    if (g_idx64) {
        const long long* t = reinterpret_cast<const long long*>(tri) + 3LL * e;
        h = (int)t[0]; a = (int)t[1]; v = (int)t[2];
    } else {
        const int* t = reinterpret_cast<const int*>(tri) + 3 * e;
        h = t[0]; a = t[1]; v = t[2];
    }
    float s = g_sent[h] + g_satt[a] + __ldg(&ab[0]);
    s = s > 0.f ? s : 0.2f * s;                 // leaky_relu(0.2)
    float sc = __expf(s);
    atomicAdd(&g_rowsum[h], sc);
    atomicAdd(&g_deg[h], 1);
    g_packed[e] = make_int4(h, a, v, __float_as_int(sc));
}

// ---------------- 3-phase exclusive scan over degrees -----------------------
__global__ void scan_a_kernel() {
    __shared__ int sh[256];
    int t = threadIdx.x, b = blockIdx.x;
    int node = b * 256 + t;
    sh[t] = (node < N_NODES) ? g_deg[node] : 0;
    __syncthreads();
    #pragma unroll
    for (int d = 128; d; d >>= 1) {
        if (t < d) sh[t] += sh[t + d];
        __syncthreads();
    }
    if (t == 0) g_bsum[b] = sh[0];
}

__global__ void scan_b_kernel() {
    __shared__ int sh[512];
    int t = threadIdx.x;
    int v = (t < NBLK) ? g_bsum[t] : 0;
    sh[t] = v;
    __syncthreads();
    #pragma unroll
    for (int d = 1; d < 512; d <<= 1) {
        int x = (t >= d) ? sh[t - d] : 0;
        __syncthreads();
        sh[t] += x;
        __syncthreads();
    }
    if (t < NBLK) g_boff[t] = sh[t] - v;   // exclusive
}

__global__ void scan_c_kernel() {
    __shared__ int sh[256];
    int t = threadIdx.x, b = blockIdx.x;
    int node = b * 256 + t;
    int v = (node < N_NODES) ? g_deg[node] : 0;
    sh[t] = v;
    __syncthreads();
    #pragma unroll
    for (int d = 1; d < 256; d <<= 1) {
        int x = (t >= d) ? sh[t - d] : 0;
        __syncthreads();
        sh[t] += x;
        __syncthreads();
    }
    if (node < N_NODES) {
        int off = g_boff[b] + sh[t] - v;
        g_off[node] = off;
        g_cursor[node] = off;
    }
}

// ---------------- pass B: permute records into CSR order --------------------
__global__ void fill_kernel() {
    int e = blockIdx.x * blockDim.x + threadIdx.x;
    if (e >= N_EDGES) return;
    int4 p = g_packed[e];
    int pos = atomicAdd(&g_cursor[p.x], 1);
    g_csr[pos] = p;
}

// ------- pass C: gather-side weighted aggregation -> fp16 rows --------------
__device__ __forceinline__ void acc_edge(uint2 ua, uint2 uv, float s, int lane,
                                         float4& accA, float4& accV) {
    __half2 h0 = *reinterpret_cast<__half2*>(&ua.x);
    __half2 h1 = *reinterpret_cast<__half2*>(&ua.y);
    float2 f0 = __half22float2(h0);
    float2 f1 = __half22float2(h1);
    accA.x += f0.x * s; accA.y += f0.y * s;
    accA.z += f1.x * s; accA.w += f1.y * s;
    if (lane < 16) {
        __half2 g0 = *reinterpret_cast<__half2*>(&uv.x);
        __half2 g1 = *reinterpret_cast<__half2*>(&uv.y);
        float2 e0 = __half22float2(g0);
        float2 e1 = __half22float2(g1);
        accV.x += e0.x * s; accV.y += e0.y * s;
        accV.z += e1.x * s; accV.w += e1.y * s;
    }
}

__global__ void aggregate_kernel() {
    int warp = (blockIdx.x * blockDim.x + threadIdx.x) >> 5;
    int lane = threadIdx.x & 31;
    if (warp >= N_NODES) return;
    int beg = g_off[warp];
    int deg = g_deg[warp];

    float4 accA = make_float4(0.f, 0.f, 0.f, 0.f);
    float4 accV = make_float4(0.f, 0.f, 0.f, 0.f);

    for (int base = 0; base < deg; base += 32) {
        int4 r = make_int4(0, 0, 0, 0);
        if (base + lane < deg) r = g_csr[beg + base + lane];
        int m = min(32, deg - base);
        int i = 0;
        for (; i + 8 <= m; i += 8) {
            uint2 UA[8], UV[8];
            float S[8];
            #pragma unroll
            for (int u = 0; u < 8; u++) {
                int a = __shfl_sync(0xFFFFFFFFu, r.y, i + u);
                int v = __shfl_sync(0xFFFFFFFFu, r.z, i + u);
                S[u]  = __int_as_float(__shfl_sync(0xFFFFFFFFu, r.w, i + u));
                UA[u] = *reinterpret_cast<const uint2*>(g_attH + a * KD + lane * 4);
                UV[u] = (lane < 16)
                    ? *reinterpret_cast<const uint2*>(g_valH + v * VD + lane * 4)
                    : make_uint2(0u, 0u);
            }
            #pragma unroll
            for (int u = 0; u < 8; u++)
                acc_edge(UA[u], UV[u], S[u], lane, accA, accV);
        }
        for (; i < m; i++) {
            int a = __shfl_sync(0xFFFFFFFFu, r.y, i);
            int v = __shfl_sync(0xFFFFFFFFu, r.z, i);
            float s = __int_as_float(__shfl_sync(0xFFFFFFFFu, r.w, i));
            uint2 ua = *reinterpret_cast<const uint2*>(g_attH + a * KD + lane * 4);
            uint2 uv = (lane < 16)
                ? *reinterpret_cast<const uint2*>(g_valH + v * VD + lane * 4)
                : make_uint2(0u, 0u);
            acc_edge(ua, uv, s, lane, accA, accV);
        }
    }

    __half* dst = g_aggH + (size_t)warp * AGGD;
    __half2 a0 = __floats2half2_rn(accA.x, accA.y);
    __half2 a1 = __floats2half2_rn(accA.z, accA.w);
    uint2 pa;
    pa.x = *reinterpret_cast<unsigned*>(&a0);
    pa.y = *reinterpret_cast<unsigned*>(&a1);
    *reinterpret_cast<uint2*>(dst + lane * 4) = pa;
    if (lane < 16) {
        __half2 v0 = __floats2half2_rn(accV.x, accV.y);
        __half2 v1 = __floats2half2_rn(accV.z, accV.w);
        uint2 pv;
        pv.x = *reinterpret_cast<unsigned*>(&v0);
        pv.y = *reinterpret_cast<unsigned*>(&v1);
        *reinterpret_cast<uint2*>(dst + KD + lane * 4) = pv;
    }
}

// ======== node GEMM via wmma (HMMA): out = elu(aggH @ W / rowsum + ent) =====
// 512 threads = 16 warps; tile = 128 nodes x 128 cols.
// Warp (rg, ch): rows rg*16..+16, cols ch*64..+64 (4 wmma n-tiles), K = 192.
// smem: A[128][192] fp16 (48KB) + Wt[128][192] fp16 (48KB) + D[128][132] f32.
#define WM_THREADS 512
#define A_BYTES (128 * AGGD * 2)            // 49152
#define D_STRIDE 132
#define SM_A 0
#define SM_W A_BYTES                        // 49152
#define SM_DST (2 * A_BYTES)                // 98304
#define WM_SMEM_TOTAL (SM_DST + 128 * D_STRIDE * 4)   // 165888

__global__ void __launch_bounds__(WM_THREADS, 1)
node_wmma_kernel(const float* __restrict__ ent, float* __restrict__ out) {
    extern __shared__ char smem[];
    __half* As = reinterpret_cast<__half*>(smem + SM_A);
    __half* Ws = reinterpret_cast<__half*>(smem + SM_W);
    float*  Ds = reinterpret_cast<float*>(smem + SM_DST);

    int tid = threadIdx.x;
    int wid = tid >> 5;
    int rg  = wid >> 1;     // row group 0..7
    int ch  = wid & 1;      // col half 0..1

    // Wt once per block (48KB)
    for (int i = tid; i < KD * AGGD / 8; i += WM_THREADS)
        reinterpret_cast<uint4*>(Ws)[i] =
            __ldg(&reinterpret_cast<const uint4*>(g_Wt)[i]);

    const float4* ent4 = reinterpret_cast<const float4*>(ent);
    float4* out4 = reinterpret_cast<float4*>(out);

    for (int tile = blockIdx.x; tile < N_TILES; tile += gridDim.x) {
        __syncthreads();   // As/Ds safe to overwrite (prev iter consumed)
        // stage A: 128 rows x 192 halves = 3072 uint4
        for (int i = tid; i < 128 * (AGGD / 8); i += WM_THREADS) {
            int row = i / (AGGD / 8);
            int off = i % (AGGD / 8);
            int node = tile * 128 + row;
            uint4 v = make_uint4(0u, 0u, 0u, 0u);
            if (node < N_NODES)
                v = __ldg(reinterpret_cast<const uint4*>(
                        g_aggH + (size_t)node * AGGD) + off);
            reinterpret_cast<uint4*>(As)[i] = v;
        }
        __syncthreads();

        wmma::fragment<wmma::accumulator, 16, 16, 16, float> acc[4];
        #pragma unroll
        for (int n = 0; n < 4; n++) wmma::fill_fragment(acc[n], 0.f);

        #pragma unroll
        for (int k = 0; k < AGGD; k += 16) {
            wmma::fragment<wmma::matrix_a, 16, 16, 16, __half, wmma::row_major> a;
            wmma::load_matrix_sync(a, As + rg * 16 * AGGD + k, AGGD);
            #pragma unroll
            for (int n = 0; n < 4; n++) {
                wmma::fragment<wmma::matrix_b, 16, 16, 16, __half, wmma::col_major> b;
                wmma::load_matrix_sync(b, Ws + (ch * 64 + n * 16) * AGGD + k, AGGD);
                wmma::mma_sync(acc[n], a, b, acc[n]);
            }
        }

        #pragma unroll
        for (int n = 0; n < 4; n++)
            wmma::store_matrix_sync(Ds + rg * 16 * D_STRIDE + ch * 64 + n * 16,
                                    acc[n], D_STRIDE, wmma::mem_row_major);
        __syncthreads();

        // coalesced epilogue: 128 rows x 32 float4 = 4096 units, 8 per thread
        #pragma unroll
        for (int it = 0; it < 8; it++) {
            int idx = tid + it * WM_THREADS;   // 0..4095
            int row = idx >> 5;
            int cg  = idx & 31;
            int node = tile * 128 + row;
            if (node < N_NODES) {
                float4 dv = *reinterpret_cast<const float4*>(
                    Ds + row * D_STRIDE + cg * 4);
                float rs = g_rowsum[node];
                float inv = rs > 0.f ? 1.f / rs : 0.f;
                float4 e = __ldg(&ent4[node * 32 + cg]);
                float t0 = dv.x * inv + e.x;
                float t1 = dv.y * inv + e.y;
                float t2 = dv.z * inv + e.z;
                float t3 = dv.w * inv + e.w;
                float4 o;
                o.x = t0 > 0.f ? t0 : expm1f(t0);   // elu, alpha=1
                o.y = t1 > 0.f ? t1 : expm1f(t1);
                o.z = t2 > 0.f ? t2 : expm1f(t2);
                o.w = t3 > 0.f ? t3 : expm1f(t3);
                out4[node * 32 + cg] = o;
            }
        }
    }
}

// ---------------- launch ----------------------------------------------------
extern "C" void kernel_launch(void* const* d_in, const int* in_sizes, int n_in,
                              void* d_out, int out_size) {
    const void*  triples = d_in[0];                       // [1e6, 3] int64/int32
    const float* ent     = (const float*)d_in[1];         // [1e5, 128]
    const float* attf    = (const float*)d_in[2];         // [1e5, 128]
    const float* valf    = (const float*)d_in[3];         // [1e5, 64]
    const float* aw      = (const float*)d_in[4];         // [256]
    const float* ab      = (const float*)d_in[5];         // [1]
    const float* W       = (const float*)d_in[6];         // [192, 128]
    float* out           = (float*)d_out;                 // [1e5, 128]

    static bool attr_set = false;
    if (!attr_set) {
        cudaFuncSetAttribute(node_wmma_kernel,
                             cudaFuncAttributeMaxDynamicSharedMemorySize,
                             WM_SMEM_TOTAL);
        attr_set = true;
    }

    sniff_kernel<<<1, 256>>>((const int*)triples);
    score_pre_kernel<<<(N_NODES + 7) / 8, 256>>>(ent, attf, aw);
    valconv_kernel<<<(N_NODES * VD / 4 + 255) / 256, 256>>>(valf);
    prepack_kernel<<<(KD * AGGD + 255) / 256, 256>>>(W);
    score_edge_kernel<<<(N_EDGES + 255) / 256, 256>>>(triples, ab);
    scan_a_kernel<<<NBLK, 256>>>();
    scan_b_kernel<<<1, 512>>>();
    scan_c_kernel<<<NBLK, 256>>>();
    fill_kernel<<<(N_EDGES + 255) / 256, 256>>>();
    aggregate_kernel<<<(N_NODES * 32 + 255) / 256, 256>>>();
    node_wmma_kernel<<<148, WM_THREADS, WM_SMEM_TOTAL>>>(ent, out);
}

// round 10
// speedup vs baseline: 1.3313x; 1.2778x over previous
#include <cuda_runtime.h>
#include <cuda_fp16.h>
#include <mma.h>
#include <math.h>
#include <cstdint>

using namespace nvcuda;

#define N_NODES 100000
#define N_EDGES 1000000
#define KD 128
#define VD 64
#define AGGD 192   // KD + VD
#define NBLK 391   // ceil(N_NODES / 256)
#define N_TILES 782  // ceil(N_NODES / 128)

// ---------------- scratch (static device allocations, graph-safe) ----------
__device__ __align__(16) int4   g_packed[N_EDGES];   // {h, a, v, bitcast(score)}
__device__ __align__(16) int4   g_csr[N_EDGES];      // CSR-ordered copies
__device__ __align__(16) __half g_attH[N_NODES * KD];
__device__ __align__(16) __half g_valH[N_NODES * VD];
__device__ __align__(16) __half g_aggH[N_NODES * AGGD];  // fp16 aggregated rows
__device__ __align__(16) __half g_Wt[KD * AGGD];         // Wt[n][k] = W[k][n]
__device__ float g_rowsum[N_NODES];
__device__ float g_sent[N_NODES];
__device__ float g_satt[N_NODES];
__device__ int   g_deg[N_NODES];
__device__ int   g_off[N_NODES];
__device__ int   g_cursor[N_NODES];
__device__ int   g_bsum[NBLK];
__device__ int   g_boff[NBLK];
__device__ int   g_idx64;

// ---------------- dtype sniff: int64 vs int32 triples (parallel) -----------
__global__ void sniff_kernel(const int* tri32) {
    int t = threadIdx.x;
    int bad = (tri32[2 * t + 1] != 0) ? 1 : 0;
    int any = __syncthreads_or(bad);
    if (t == 0) g_idx64 = any ? 0 : 1;
}

// ------- per-node score pre-reduction + att fp16 conversion + resets --------
__global__ void score_pre_kernel(const float* __restrict__ ent,
                                 const float* __restrict__ att,
                                 const float* __restrict__ aw) {
    int warp = (blockIdx.x * blockDim.x + threadIdx.x) >> 5;
    int lane = threadIdx.x & 31;
    if (warp >= N_NODES) return;

    const float4* ent4 = reinterpret_cast<const float4*>(ent);
    const float4* att4 = reinterpret_cast<const float4*>(att);
    const float4* aw4  = reinterpret_cast<const float4*>(aw);

    float4 e = ent4[warp * 32 + lane];
    float4 a = att4[warp * 32 + lane];
    float4 we = __ldg(&aw4[lane]);
    float4 wa = __ldg(&aw4[32 + lane]);

    __half2 h0 = __floats2half2_rn(a.x, a.y);
    __half2 h1 = __floats2half2_rn(a.z, a.w);
    uint2 packed;
    packed.x = *reinterpret_cast<unsigned*>(&h0);
    packed.y = *reinterpret_cast<unsigned*>(&h1);
    *reinterpret_cast<uint2*>(g_attH + warp * KD + lane * 4) = packed;

    float se = e.x * we.x + e.y * we.y + e.z * we.z + e.w * we.w;
    float sa = a.x * wa.x + a.y * wa.y + a.z * wa.z + a.w * wa.w;
    #pragma unroll
    for (int o = 16; o; o >>= 1) {
        se += __shfl_xor_sync(0xFFFFFFFFu, se, o);
        sa += __shfl_xor_sync(0xFFFFFFFFu, sa, o);
    }
    if (lane == 0) {
        g_sent[warp] = se;
        g_satt[warp] = sa;
        g_rowsum[warp] = 0.f;
        g_deg[warp] = 0;
    }
}

// ---------------- val fp16 conversion ---------------------------------------
__global__ void valconv_kernel(const float* __restrict__ valf) {
    int i = blockIdx.x * blockDim.x + threadIdx.x;
    int n4 = N_NODES * VD / 4;
    if (i >= n4) return;
    float4 v = reinterpret_cast<const float4*>(valf)[i];
    __half2 h0 = __floats2half2_rn(v.x, v.y);
    __half2 h1 = __floats2half2_rn(v.z, v.w);
    uint2 packed;
    packed.x = *reinterpret_cast<unsigned*>(&h0);
    packed.y = *reinterpret_cast<unsigned*>(&h1);
    *reinterpret_cast<uint2*>(g_valH + i * 4) = packed;
}

// ---------------- prepack W^T as fp16: Wt[n][k] = W[k][n] -------------------
__global__ void prepack_kernel(const float* __restrict__ W) {
    int idx = blockIdx.x * blockDim.x + threadIdx.x;
    if (idx >= KD * AGGD) return;
    int n = idx / AGGD;        // 0..127
    int k = idx % AGGD;        // 0..191
    g_Wt[idx] = __float2half_rn(W[k * KD + n]);
}

// ---------------- pass A: per-edge score + degree histogram -----------------
__global__ void score_edge_kernel(const void* __restrict__ tri,
                                  const float* __restrict__ ab) {
    int e = blockIdx.x * blockDim.x + threadIdx.x;
    if (e >= N_EDGES) return;
    int h, a, v;
    if (g_idx64) {
        const long long* t = reinterpret_cast<const long long*>(tri) + 3LL * e;
        h = (int)t[0]; a = (int)t[1]; v = (int)t[2];
    } else {
        const int* t = reinterpret_cast<const int*>(tri) + 3 * e;
        h = t[0]; a = t[1]; v = t[2];
    }
    float s = g_sent[h] + g_satt[a] + __ldg(&ab[0]);
    s = s > 0.f ? s : 0.2f * s;                 // leaky_relu(0.2)
    float sc = __expf(s);
    atomicAdd(&g_rowsum[h], sc);
    atomicAdd(&g_deg[h], 1);
    g_packed[e] = make_int4(h, a, v, __float_as_int(sc));
}

// ---------------- 3-phase exclusive scan over degrees -----------------------
__global__ void scan_a_kernel() {
    __shared__ int sh[256];
    int t = threadIdx.x, b = blockIdx.x;
    int node = b * 256 + t;
    sh[t] = (node < N_NODES) ? g_deg[node] : 0;
    __syncthreads();
    #pragma unroll
    for (int d = 128; d; d >>= 1) {
        if (t < d) sh[t] += sh[t + d];
        __syncthreads();
    }
    if (t == 0) g_bsum[b] = sh[0];
}

__global__ void scan_b_kernel() {
    __shared__ int sh[512];
    int t = threadIdx.x;
    int v = (t < NBLK) ? g_bsum[t] : 0;
    sh[t] = v;
    __syncthreads();
    #pragma unroll
    for (int d = 1; d < 512; d <<= 1) {
        int x = (t >= d) ? sh[t - d] : 0;
        __syncthreads();
        sh[t] += x;
        __syncthreads();
    }
    if (t < NBLK) g_boff[t] = sh[t] - v;   // exclusive
}

__global__ void scan_c_kernel() {
    __shared__ int sh[256];
    int t = threadIdx.x, b = blockIdx.x;
    int node = b * 256 + t;
    int v = (node < N_NODES) ? g_deg[node] : 0;
    sh[t] = v;
    __syncthreads();
    #pragma unroll
    for (int d = 1; d < 256; d <<= 1) {
        int x = (t >= d) ? sh[t - d] : 0;
        __syncthreads();
        sh[t] += x;
        __syncthreads();
    }
    if (node < N_NODES) {
        int off = g_boff[b] + sh[t] - v;
        g_off[node] = off;
        g_cursor[node] = off;
    }
}

// ---------------- pass B: permute records into CSR order --------------------
__global__ void fill_kernel() {
    int e = blockIdx.x * blockDim.x + threadIdx.x;
    if (e >= N_EDGES) return;
    int4 p = g_packed[e];
    int pos = atomicAdd(&g_cursor[p.x], 1);
    g_csr[pos] = p;
}

// ------- pass C: gather-side weighted aggregation -> fp16 rows --------------
__device__ __forceinline__ void acc_edge(uint2 ua, uint2 uv, float s, int lane,
                                         float4& accA, float4& accV) {
    __half2 h0 = *reinterpret_cast<__half2*>(&ua.x);
    __half2 h1 = *reinterpret_cast<__half2*>(&ua.y);
    float2 f0 = __half22float2(h0);
    float2 f1 = __half22float2(h1);
    accA.x += f0.x * s; accA.y += f0.y * s;
    accA.z += f1.x * s; accA.w += f1.y * s;
    if (lane < 16) {
        __half2 g0 = *reinterpret_cast<__half2*>(&uv.x);
        __half2 g1 = *reinterpret_cast<__half2*>(&uv.y);
        float2 e0 = __half22float2(g0);
        float2 e1 = __half22float2(g1);
        accV.x += e0.x * s; accV.y += e0.y * s;
        accV.z += e1.x * s; accV.w += e1.y * s;
    }
}

__global__ void aggregate_kernel() {
    int warp = (blockIdx.x * blockDim.x + threadIdx.x) >> 5;
    int lane = threadIdx.x & 31;
    if (warp >= N_NODES) return;
    int beg = g_off[warp];
    int deg = g_deg[warp];

    float4 accA = make_float4(0.f, 0.f, 0.f, 0.f);
    float4 accV = make_float4(0.f, 0.f, 0.f, 0.f);

    for (int base = 0; base < deg; base += 32) {
        int4 r = make_int4(0, 0, 0, 0);
        if (base + lane < deg) r = g_csr[beg + base + lane];
        int m = min(32, deg - base);
        int i = 0;
        for (; i + 8 <= m; i += 8) {
            uint2 UA[8], UV[8];
            float S[8];
            #pragma unroll
            for (int u = 0; u < 8; u++) {
                int a = __shfl_sync(0xFFFFFFFFu, r.y, i + u);
                int v = __shfl_sync(0xFFFFFFFFu, r.z, i + u);
                S[u]  = __int_as_float(__shfl_sync(0xFFFFFFFFu, r.w, i + u));
                UA[u] = *reinterpret_cast<const uint2*>(g_attH + a * KD + lane * 4);
                UV[u] = (lane < 16)
                    ? *reinterpret_cast<const uint2*>(g_valH + v * VD + lane * 4)
                    : make_uint2(0u, 0u);
            }
            #pragma unroll
            for (int u = 0; u < 8; u++)
                acc_edge(UA[u], UV[u], S[u], lane, accA, accV);
        }
        for (; i < m; i++) {
            int a = __shfl_sync(0xFFFFFFFFu, r.y, i);
            int v = __shfl_sync(0xFFFFFFFFu, r.z, i);
            float s = __int_as_float(__shfl_sync(0xFFFFFFFFu, r.w, i));
            uint2 ua = *reinterpret_cast<const uint2*>(g_attH + a * KD + lane * 4);
            uint2 uv = (lane < 16)
                ? *reinterpret_cast<const uint2*>(g_valH + v * VD + lane * 4)
                : make_uint2(0u, 0u);
            acc_edge(ua, uv, s, lane, accA, accV);
        }
    }

    __half* dst = g_aggH + (size_t)warp * AGGD;
    __half2 a0 = __floats2half2_rn(accA.x, accA.y);
    __half2 a1 = __floats2half2_rn(accA.z, accA.w);
    uint2 pa;
    pa.x = *reinterpret_cast<unsigned*>(&a0);
    pa.y = *reinterpret_cast<unsigned*>(&a1);
    *reinterpret_cast<uint2*>(dst + lane * 4) = pa;
    if (lane < 16) {
        __half2 v0 = __floats2half2_rn(accV.x, accV.y);
        __half2 v1 = __floats2half2_rn(accV.z, accV.w);
        uint2 pv;
        pv.x = *reinterpret_cast<unsigned*>(&v0);
        pv.y = *reinterpret_cast<unsigned*>(&v1);
        *reinterpret_cast<uint2*>(dst + KD + lane * 4) = pv;
    }
}

// ======== node GEMM via wmma (HMMA): out = elu(aggH @ W / rowsum + ent) =====
// 512 threads = 16 warps; tile = 128 nodes x 128 cols.
// smem strides PADDED: A/W rows = 200 halves (400B == 4 mod 32 banks ->
// conflict-free fragment loads; 16B multiple -> wmma-legal). D = 132 floats.
#define WM_THREADS 512
#define A_STRIDE 200                        // halves
#define D_STRIDE 132                        // floats
#define SM_A 0
#define A_BYTES (128 * A_STRIDE * 2)        // 51200
#define SM_W A_BYTES
#define SM_DST (2 * A_BYTES)                // 102400
#define WM_SMEM_TOTAL (SM_DST + 128 * D_STRIDE * 4)   // 169984

__global__ void __launch_bounds__(WM_THREADS, 1)
node_wmma_kernel(const float* __restrict__ ent, float* __restrict__ out) {
    extern __shared__ char smem[];
    __half* As = reinterpret_cast<__half*>(smem + SM_A);
    __half* Ws = reinterpret_cast<__half*>(smem + SM_W);
    float*  Ds = reinterpret_cast<float*>(smem + SM_DST);

    int tid = threadIdx.x;
    int wid = tid >> 5;
    int rg  = wid >> 1;     // row group 0..7
    int ch  = wid & 1;      // col half 0..1

    // Wt once per block: 128 rows x 24 uint4, padded stride 25 uint4
    for (int i = tid; i < 128 * 24; i += WM_THREADS) {
        int row = i / 24;
        int off = i % 24;
        reinterpret_cast<uint4*>(Ws + row * A_STRIDE)[off] =
            __ldg(&reinterpret_cast<const uint4*>(g_Wt)[row * 24 + off]);
    }

    const float4* ent4 = reinterpret_cast<const float4*>(ent);
    float4* out4 = reinterpret_cast<float4*>(out);

    for (int tile = blockIdx.x; tile < N_TILES; tile += gridDim.x) {
        __syncthreads();   // As/Ds safe to overwrite (prev iter consumed)
        // stage A: 128 rows x 24 uint4 (padded rows)
        for (int i = tid; i < 128 * 24; i += WM_THREADS) {
            int row = i / 24;
            int off = i % 24;
            int node = tile * 128 + row;
            uint4 v = make_uint4(0u, 0u, 0u, 0u);
            if (node < N_NODES)
                v = __ldg(reinterpret_cast<const uint4*>(
                        g_aggH + (size_t)node * AGGD) + off);
            reinterpret_cast<uint4*>(As + row * A_STRIDE)[off] = v;
        }
        __syncthreads();

        wmma::fragment<wmma::accumulator, 16, 16, 16, float> acc[4];
        #pragma unroll
        for (int n = 0; n < 4; n++) wmma::fill_fragment(acc[n], 0.f);

        #pragma unroll
        for (int k = 0; k < AGGD; k += 16) {
            wmma::fragment<wmma::matrix_a, 16, 16, 16, __half, wmma::row_major> a;
            wmma::load_matrix_sync(a, As + rg * 16 * A_STRIDE + k, A_STRIDE);
            #pragma unroll
            for (int n = 0; n < 4; n++) {
                wmma::fragment<wmma::matrix_b, 16, 16, 16, __half, wmma::col_major> b;
                wmma::load_matrix_sync(b, Ws + (ch * 64 + n * 16) * A_STRIDE + k,
                                       A_STRIDE);
                wmma::mma_sync(acc[n], a, b, acc[n]);
            }
        }

        #pragma unroll
        for (int n = 0; n < 4; n++)
            wmma::store_matrix_sync(Ds + rg * 16 * D_STRIDE + ch * 64 + n * 16,
                                    acc[n], D_STRIDE, wmma::mem_row_major);
        __syncthreads();

        // coalesced epilogue: 128 rows x 32 float4 = 4096 units, 8 per thread
        #pragma unroll
        for (int it = 0; it < 8; it++) {
            int idx = tid + it * WM_THREADS;   // 0..4095
            int row = idx >> 5;
            int cg  = idx & 31;
            int node = tile * 128 + row;
            if (node < N_NODES) {
                float4 dv = *reinterpret_cast<const float4*>(
                    Ds + row * D_STRIDE + cg * 4);
                float rs = g_rowsum[node];
                float inv = rs > 0.f ? 1.f / rs : 0.f;
                float4 e = __ldg(&ent4[node * 32 + cg]);
                float t0 = dv.x * inv + e.x;
                float t1 = dv.y * inv + e.y;
                float t2 = dv.z * inv + e.z;
                float t3 = dv.w * inv + e.w;
                float4 o;
                o.x = t0 > 0.f ? t0 : expm1f(t0);   // elu, alpha=1
                o.y = t1 > 0.f ? t1 : expm1f(t1);
                o.z = t2 > 0.f ? t2 : expm1f(t2);
                o.w = t3 > 0.f ? t3 : expm1f(t3);
                out4[node * 32 + cg] = o;
            }
        }
    }
}

// ---------------- launch ----------------------------------------------------
extern "C" void kernel_launch(void* const* d_in, const int* in_sizes, int n_in,
                              void* d_out, int out_size) {
    const void*  triples = d_in[0];                       // [1e6, 3] int64/int32
    const float* ent     = (const float*)d_in[1];         // [1e5, 128]
    const float* attf    = (const float*)d_in[2];         // [1e5, 128]
    const float* valf    = (const float*)d_in[3];         // [1e5, 64]
    const float* aw      = (const float*)d_in[4];         // [256]
    const float* ab      = (const float*)d_in[5];         // [1]
    const float* W       = (const float*)d_in[6];         // [192, 128]
    float* out           = (float*)d_out;                 // [1e5, 128]

    static bool attr_set = false;
    if (!attr_set) {
        cudaFuncSetAttribute(node_wmma_kernel,
                             cudaFuncAttributeMaxDynamicSharedMemorySize,
                             WM_SMEM_TOTAL);
        attr_set = true;
    }

    // order chosen so the ncu slot (4th launch) captures score_pre_kernel
    sniff_kernel<<<1, 256>>>((const int*)triples);
    valconv_kernel<<<(N_NODES * VD / 4 + 255) / 256, 256>>>(valf);
    prepack_kernel<<<(KD * AGGD + 255) / 256, 256>>>(W);
    score_pre_kernel<<<(N_NODES + 7) / 8, 256>>>(ent, attf, aw);
    score_edge_kernel<<<(N_EDGES + 255) / 256, 256>>>(triples, ab);
    scan_a_kernel<<<NBLK, 256>>>();
    scan_b_kernel<<<1, 512>>>();
    scan_c_kernel<<<NBLK, 256>>>();
    fill_kernel<<<(N_EDGES + 255) / 256, 256>>>();
    aggregate_kernel<<<(N_NODES * 32 + 255) / 256, 256>>>();
    node_wmma_kernel<<<148, WM_THREADS, WM_SMEM_TOTAL>>>(ent, out);
}

// round 11
// speedup vs baseline: 1.3837x; 1.0393x over previous
#include <cuda_runtime.h>
#include <cuda_fp16.h>
#include <mma.h>
#include <math.h>
#include <cstdint>

using namespace nvcuda;

#define N_NODES 100000
#define N_EDGES 1000000
#define KD 128
#define VD 64
#define AGGD 192   // KD + VD
#define NBLK 391   // ceil(N_NODES / 256)

// ---------------- scratch (static device allocations, graph-safe) ----------
__device__ __align__(16) int4   g_csr[N_EDGES];      // CSR-ordered {h,a,v,score}
__device__ __align__(16) __half g_attH[N_NODES * KD];
__device__ __align__(16) __half g_valH[N_NODES * VD];
__device__ __align__(16) __half g_aggH[N_NODES * AGGD];  // fp16 aggregated rows
__device__ __align__(16) __half g_Wt[KD * AGGD];         // Wt[n][k] = W[k][n]
__device__ float g_rowsum[N_NODES];
__device__ float g_sent[N_NODES];
__device__ float g_satt[N_NODES];
__device__ int   g_deg[N_NODES];
__device__ int   g_off[N_NODES];
__device__ int   g_cursor[N_NODES];
__device__ int   g_bsum[NBLK];
__device__ int   g_boff[NBLK];
__device__ int   g_idx64;

// ---------------- dtype sniff: int64 vs int32 triples (parallel) -----------
__global__ void sniff_kernel(const int* tri32) {
    int t = threadIdx.x;
    int bad = (tri32[2 * t + 1] != 0) ? 1 : 0;
    int any = __syncthreads_or(bad);
    if (t == 0) g_idx64 = any ? 0 : 1;
}

// ------- val fp16 conversion + per-node counter resets ----------------------
__global__ void valconv_kernel(const float* __restrict__ valf) {
    int i = blockIdx.x * blockDim.x + threadIdx.x;
    if (i < N_NODES) {
        g_deg[i] = 0;
        g_rowsum[i] = 0.f;
    }
    int n4 = N_NODES * VD / 4;
    if (i >= n4) return;
    float4 v = reinterpret_cast<const float4*>(valf)[i];
    __half2 h0 = __floats2half2_rn(v.x, v.y);
    __half2 h1 = __floats2half2_rn(v.z, v.w);
    uint2 packed;
    packed.x = *reinterpret_cast<unsigned*>(&h0);
    packed.y = *reinterpret_cast<unsigned*>(&h1);
    *reinterpret_cast<uint2*>(g_valH + i * 4) = packed;
}

// ---------------- prepack W^T as fp16: Wt[n][k] = W[k][n] -------------------
__global__ void prepack_kernel(const float* __restrict__ W) {
    int idx = blockIdx.x * blockDim.x + threadIdx.x;
    if (idx >= KD * AGGD) return;
    int n = idx / AGGD;        // 0..127
    int k = idx % AGGD;        // 0..191
    g_Wt[idx] = __float2half_rn(W[k * KD + n]);
}

// ---------------- degree histogram (h column only) ---------------------------
__global__ void deg_kernel(const int* __restrict__ tri32) {
    int e = blockIdx.x * blockDim.x + threadIdx.x;
    if (e >= N_EDGES) return;
    int h = g_idx64 ? tri32[6 * e] : tri32[3 * e];
    atomicAdd(&g_deg[h], 1);
}

// ------- per-node score pre-reduction + att fp16 conversion ----------------
__global__ void score_pre_kernel(const float* __restrict__ ent,
                                 const float* __restrict__ att,
                                 const float* __restrict__ aw) {
    int warp = (blockIdx.x * blockDim.x + threadIdx.x) >> 5;
    int lane = threadIdx.x & 31;
    if (warp >= N_NODES) return;

    const float4* ent4 = reinterpret_cast<const float4*>(ent);
    const float4* att4 = reinterpret_cast<const float4*>(att);
    const float4* aw4  = reinterpret_cast<const float4*>(aw);

    float4 e = ent4[warp * 32 + lane];
    float4 a = att4[warp * 32 + lane];
    float4 we = __ldg(&aw4[lane]);
    float4 wa = __ldg(&aw4[32 + lane]);

    __half2 h0 = __floats2half2_rn(a.x, a.y);
    __half2 h1 = __floats2half2_rn(a.z, a.w);
    uint2 packed;
    packed.x = *reinterpret_cast<unsigned*>(&h0);
    packed.y = *reinterpret_cast<unsigned*>(&h1);
    *reinterpret_cast<uint2*>(g_attH + warp * KD + lane * 4) = packed;

    float se = e.x * we.x + e.y * we.y + e.z * we.z + e.w * we.w;
    float sa = a.x * wa.x + a.y * wa.y + a.z * wa.z + a.w * wa.w;
    #pragma unroll
    for (int o = 16; o; o >>= 1) {
        se += __shfl_xor_sync(0xFFFFFFFFu, se, o);
        sa += __shfl_xor_sync(0xFFFFFFFFu, sa, o);
    }
    if (lane == 0) {
        g_sent[warp] = se;
        g_satt[warp] = sa;
    }
}

// ---------------- 3-phase exclusive scan over degrees -----------------------
__global__ void scan_a_kernel() {
    __shared__ int sh[256];
    int t = threadIdx.x, b = blockIdx.x;
    int node = b * 256 + t;
    sh[t] = (node < N_NODES) ? g_deg[node] : 0;
    __syncthreads();
    #pragma unroll
    for (int d = 128; d; d >>= 1) {
        if (t < d) sh[t] += sh[t + d];
        __syncthreads();
    }
    if (t == 0) g_bsum[b] = sh[0];
}

__global__ void scan_b_kernel() {
    __shared__ int sh[512];
    int t = threadIdx.x;
    int v = (t < NBLK) ? g_bsum[t] : 0;
    sh[t] = v;
    __syncthreads();
    #pragma unroll
    for (int d = 1; d < 512; d <<= 1) {
        int x = (t >= d) ? sh[t - d] : 0;
        __syncthreads();
        sh[t] += x;
        __syncthreads();
    }
    if (t < NBLK) g_boff[t] = sh[t] - v;   // exclusive
}

__global__ void scan_c_kernel() {
    __shared__ int sh[256];
    int t = threadIdx.x, b = blockIdx.x;
    int node = b * 256 + t;
    int v = (node < N_NODES) ? g_deg[node] : 0;
    sh[t] = v;
    __syncthreads();
    #pragma unroll
    for (int d = 1; d < 256; d <<= 1) {
        int x = (t >= d) ? sh[t - d] : 0;
        __syncthreads();
        sh[t] += x;
        __syncthreads();
    }
    if (node < N_NODES) {
        int off = g_boff[b] + sh[t] - v;
        g_off[node] = off;
        g_cursor[node] = off;
    }
}

// ------- fused score + CSR fill: compute score, write record in place -------
__global__ void score_fill_kernel(const void* __restrict__ tri,
                                  const float* __restrict__ ab) {
    int e = blockIdx.x * blockDim.x + threadIdx.x;
    if (e >= N_EDGES) return;
    int h, a, v;
    if (g_idx64) {
        const long long* t = reinterpret_cast<const long long*>(tri) + 3LL * e;
        h = (int)t[0]; a = (int)t[1]; v = (int)t[2];
    } else {
        const int* t = reinterpret_cast<const int*>(tri) + 3 * e;
        h = t[0]; a = t[1]; v = t[2];
    }
    float s = g_sent[h] + g_satt[a] + __ldg(&ab[0]);
    s = s > 0.f ? s : 0.2f * s;                 // leaky_relu(0.2)
    float sc = __expf(s);
    atomicAdd(&g_rowsum[h], sc);
    int pos = atomicAdd(&g_cursor[h], 1);
    g_csr[pos] = make_int4(h, a, v, __float_as_int(sc));
}

// ------- gather-side weighted aggregation -> fp16 rows -----------------------
__device__ __forceinline__ void acc_edge(uint2 ua, uint2 uv, float s, int lane,
                                         float4& accA, float4& accV) {
    __half2 h0 = *reinterpret_cast<__half2*>(&ua.x);
    __half2 h1 = *reinterpret_cast<__half2*>(&ua.y);
    float2 f0 = __half22float2(h0);
    float2 f1 = __half22float2(h1);
    accA.x += f0.x * s; accA.y += f0.y * s;
    accA.z += f1.x * s; accA.w += f1.y * s;
    if (lane < 16) {
        __half2 g0 = *reinterpret_cast<__half2*>(&uv.x);
        __half2 g1 = *reinterpret_cast<__half2*>(&uv.y);
        float2 e0 = __half22float2(g0);
        float2 e1 = __half22float2(g1);
        accV.x += e0.x * s; accV.y += e0.y * s;
        accV.z += e1.x * s; accV.w += e1.y * s;
    }
}

__global__ void aggregate_kernel() {
    int warp = (blockIdx.x * blockDim.x + threadIdx.x) >> 5;
    int lane = threadIdx.x & 31;
    if (warp >= N_NODES) return;
    int beg = g_off[warp];
    int deg = g_deg[warp];

    float4 accA = make_float4(0.f, 0.f, 0.f, 0.f);
    float4 accV = make_float4(0.f, 0.f, 0.f, 0.f);

    for (int base = 0; base < deg; base += 32) {
        int4 r = make_int4(0, 0, 0, 0);
        if (base + lane < deg) r = g_csr[beg + base + lane];
        int m = min(32, deg - base);
        int i = 0;
        for (; i + 8 <= m; i += 8) {
            uint2 UA[8], UV[8];
            float S[8];
            #pragma unroll
            for (int u = 0; u < 8; u++) {
                int a = __shfl_sync(0xFFFFFFFFu, r.y, i + u);
                int v = __shfl_sync(0xFFFFFFFFu, r.z, i + u);
                S[u]  = __int_as_float(__shfl_sync(0xFFFFFFFFu, r.w, i + u));
                UA[u] = *reinterpret_cast<const uint2*>(g_attH + a * KD + lane * 4);
                UV[u] = (lane < 16)
                    ? *reinterpret_cast<const uint2*>(g_valH + v * VD + lane * 4)
                    : make_uint2(0u, 0u);
            }
            #pragma unroll
            for (int u = 0; u < 8; u++)
                acc_edge(UA[u], UV[u], S[u], lane, accA, accV);
        }
        for (; i < m; i++) {
            int a = __shfl_sync(0xFFFFFFFFu, r.y, i);
            int v = __shfl_sync(0xFFFFFFFFu, r.z, i);
            float s = __int_as_float(__shfl_sync(0xFFFFFFFFu, r.w, i));
            uint2 ua = *reinterpret_cast<const uint2*>(g_attH + a * KD + lane * 4);
            uint2 uv = (lane < 16)
                ? *reinterpret_cast<const uint2*>(g_valH + v * VD + lane * 4)
                : make_uint2(0u, 0u);
            acc_edge(ua, uv, s, lane, accA, accV);
        }
    }

    __half* dst = g_aggH + (size_t)warp * AGGD;
    __half2 a0 = __floats2half2_rn(accA.x, accA.y);
    __half2 a1 = __floats2half2_rn(accA.z, accA.w);
    uint2 pa;
    pa.x = *reinterpret_cast<unsigned*>(&a0);
    pa.y = *reinterpret_cast<unsigned*>(&a1);
    *reinterpret_cast<uint2*>(dst + lane * 4) = pa;
    if (lane < 16) {
        __half2 v0 = __floats2half2_rn(accV.x, accV.y);
        __half2 v1 = __floats2half2_rn(accV.z, accV.w);
        uint2 pv;
        pv.x = *reinterpret_cast<unsigned*>(&v0);
        pv.y = *reinterpret_cast<unsigned*>(&v1);
        *reinterpret_cast<uint2*>(dst + KD + lane * 4) = pv;
    }
}

// ======== node GEMM via wmma (HMMA): out = elu(aggH @ W / rowsum + ent) =====
// 256 threads = 8 warps; tile = 64 nodes x 128 cols; 2 CTAs/SM for overlap.
// A/W smem rows padded to 200 halves (400B == 4 mod 32 banks, conflict-free).
#define WM_THREADS 256
#define TILE_ROWS 64
#define N_TILES 1563                        // ceil(100000 / 64)
#define A_STRIDE 200                        // halves
#define D_STRIDE 132                        // floats
#define SM_A 0
#define A_BYTES (TILE_ROWS * A_STRIDE * 2)  // 25600
#define SM_W A_BYTES
#define W_BYTES (KD * A_STRIDE * 2)         // 51200
#define SM_DST (SM_W + W_BYTES)             // 76800
#define WM_SMEM_TOTAL (SM_DST + TILE_ROWS * D_STRIDE * 4)   // 110592

__global__ void __launch_bounds__(WM_THREADS, 2)
node_wmma_kernel(const float* __restrict__ ent, float* __restrict__ out) {
    extern __shared__ char smem[];
    __half* As = reinterpret_cast<__half*>(smem + SM_A);
    __half* Ws = reinterpret_cast<__half*>(smem + SM_W);
    float*  Ds = reinterpret_cast<float*>(smem + SM_DST);

    int tid = threadIdx.x;
    int wid = tid >> 5;
    int rg  = wid >> 1;     // row group 0..3
    int ch  = wid & 1;      // col half 0..1

    // Wt once per block: 128 rows x 24 uint4, padded stride 25 uint4
    for (int i = tid; i < 128 * 24; i += WM_THREADS) {
        int row = i / 24;
        int off = i % 24;
        reinterpret_cast<uint4*>(Ws + row * A_STRIDE)[off] =
            __ldg(&reinterpret_cast<const uint4*>(g_Wt)[row * 24 + off]);
    }

    const float4* ent4 = reinterpret_cast<const float4*>(ent);
    float4* out4 = reinterpret_cast<float4*>(out);

    for (int tile = blockIdx.x; tile < N_TILES; tile += gridDim.x) {
        __syncthreads();   // As/Ds safe to overwrite (prev iter consumed)
        // stage A: 64 rows x 24 uint4 (padded rows)
        for (int i = tid; i < TILE_ROWS * 24; i += WM_THREADS) {
            int row = i / 24;
            int off = i % 24;
            int node = tile * TILE_ROWS + row;
            uint4 v = make_uint4(0u, 0u, 0u, 0u);
            if (node < N_NODES)
                v = __ldg(reinterpret_cast<const uint4*>(
                        g_aggH + (size_t)node * AGGD) + off);
            reinterpret_cast<uint4*>(As + row * A_STRIDE)[off] = v;
        }
        __syncthreads();

        wmma::fragment<wmma::accumulator, 16, 16, 16, float> acc[4];
        #pragma unroll
        for (int n = 0; n < 4; n++) wmma::fill_fragment(acc[n], 0.f);

        #pragma unroll
        for (int k = 0; k < AGGD; k += 16) {
            wmma::fragment<wmma::matrix_a, 16, 16, 16, __half, wmma::row_major> a;
            wmma::load_matrix_sync(a, As + rg * 16 * A_STRIDE + k, A_STRIDE);
            #pragma unroll
            for (int n = 0; n < 4; n++) {
                wmma::fragment<wmma::matrix_b, 16, 16, 16, __half, wmma::col_major> b;
                wmma::load_matrix_sync(b, Ws + (ch * 64 + n * 16) * A_STRIDE + k,
                                       A_STRIDE);
                wmma::mma_sync(acc[n], a, b, acc[n]);
            }
        }

        #pragma unroll
        for (int n = 0; n < 4; n++)
            wmma::store_matrix_sync(Ds + rg * 16 * D_STRIDE + ch * 64 + n * 16,
                                    acc[n], D_STRIDE, wmma::mem_row_major);
        __syncthreads();

        // coalesced epilogue: 64 rows x 32 float4 = 2048 units, 8 per thread
        #pragma unroll
        for (int it = 0; it < 8; it++) {
            int idx = tid + it * WM_THREADS;   // 0..2047
            int row = idx >> 5;
            int cg  = idx & 31;
            int node = tile * TILE_ROWS + row;
            if (node < N_NODES) {
                float4 dv = *reinterpret_cast<const float4*>(
                    Ds + row * D_STRIDE + cg * 4);
                float rs = g_rowsum[node];
                float inv = rs > 0.f ? 1.f / rs : 0.f;
                float4 e = __ldg(&ent4[node * 32 + cg]);
                float t0 = dv.x * inv + e.x;
                float t1 = dv.y * inv + e.y;
                float t2 = dv.z * inv + e.z;
                float t3 = dv.w * inv + e.w;
                float4 o;
                o.x = t0 > 0.f ? t0 : expm1f(t0);   // elu, alpha=1
                o.y = t1 > 0.f ? t1 : expm1f(t1);
                o.z = t2 > 0.f ? t2 : expm1f(t2);
                o.w = t3 > 0.f ? t3 : expm1f(t3);
                out4[node * 32 + cg] = o;
            }
        }
    }
}

// ---------------- launch ----------------------------------------------------
extern "C" void kernel_launch(void* const* d_in, const int* in_sizes, int n_in,
                              void* d_out, int out_size) {
    const void*  triples = d_in[0];                       // [1e6, 3] int64/int32
    const float* ent     = (const float*)d_in[1];         // [1e5, 128]
    const float* attf    = (const float*)d_in[2];         // [1e5, 128]
    const float* valf    = (const float*)d_in[3];         // [1e5, 64]
    const float* aw      = (const float*)d_in[4];         // [256]
    const float* ab      = (const float*)d_in[5];         // [1]
    const float* W       = (const float*)d_in[6];         // [192, 128]
    float* out           = (float*)d_out;                 // [1e5, 128]

    static bool attr_set = false;
    if (!attr_set) {
        cudaFuncSetAttribute(node_wmma_kernel,
                             cudaFuncAttributeMaxDynamicSharedMemorySize,
                             WM_SMEM_TOTAL);
        attr_set = true;
    }

    // 4th launch = deg_kernel -> profiled next round
    sniff_kernel<<<1, 256>>>((const int*)triples);
    valconv_kernel<<<(N_NODES * VD / 4 + 255) / 256, 256>>>(valf);
    prepack_kernel<<<(KD * AGGD + 255) / 256, 256>>>(W);
    deg_kernel<<<(N_EDGES + 255) / 256, 256>>>((const int*)triples);
    score_pre_kernel<<<(N_NODES + 7) / 8, 256>>>(ent, attf, aw);
    scan_a_kernel<<<NBLK, 256>>>();
    scan_b_kernel<<<1, 512>>>();
    scan_c_kernel<<<NBLK, 256>>>();
    score_fill_kernel<<<(N_EDGES + 255) / 256, 256>>>(triples, ab);
    aggregate_kernel<<<(N_NODES * 32 + 255) / 256, 256>>>();
    node_wmma_kernel<<<296, WM_THREADS, WM_SMEM_TOTAL>>>(ent, out);
}

// round 12
// speedup vs baseline: 1.4028x; 1.0138x over previous
#include <cuda_runtime.h>
#include <cuda_fp16.h>
#include <mma.h>
#include <math.h>
#include <cstdint>

using namespace nvcuda;

#define N_NODES 100000
#define N_EDGES 1000000
#define KD 128
#define VD 64
#define AGGD 192   // KD + VD
#define NBLK 391   // ceil(N_NODES / 256)

// ---------------- scratch (static device allocations, graph-safe) ----------
__device__ __align__(16) int4   g_csr[N_EDGES];      // CSR-ordered {h,a,v,score}
__device__ __align__(16) __half g_attH[N_NODES * KD];
__device__ __align__(16) __half g_valH[N_NODES * VD];
__device__ __align__(16) __half g_aggH[N_NODES * AGGD];  // fp16 aggregated rows
__device__ __align__(16) __half g_Wt[KD * AGGD];         // Wt[n][k] = W[k][n]
__device__ float g_rowsum[N_NODES];
__device__ float g_sent[N_NODES];
__device__ float g_satt[N_NODES];
__device__ int   g_deg[N_NODES];
__device__ int   g_off[N_NODES];
__device__ int   g_cursor[N_NODES];
__device__ int   g_bsum[NBLK];
__device__ int   g_boff[NBLK];
__device__ int   g_idx64;

// ---------------- dtype sniff: int64 vs int32 triples (parallel) -----------
__global__ void sniff_kernel(const int* tri32) {
    int t = threadIdx.x;
    int bad = (tri32[2 * t + 1] != 0) ? 1 : 0;
    int any = __syncthreads_or(bad);
    if (t == 0) g_idx64 = any ? 0 : 1;
}

// ------- val fp16 conversion + per-node counter resets ----------------------
__global__ void valconv_kernel(const float* __restrict__ valf) {
    int i = blockIdx.x * blockDim.x + threadIdx.x;
    if (i < N_NODES) {
        g_deg[i] = 0;
        g_rowsum[i] = 0.f;
    }
    int n4 = N_NODES * VD / 4;
    if (i >= n4) return;
    float4 v = reinterpret_cast<const float4*>(valf)[i];
    __half2 h0 = __floats2half2_rn(v.x, v.y);
    __half2 h1 = __floats2half2_rn(v.z, v.w);
    uint2 packed;
    packed.x = *reinterpret_cast<unsigned*>(&h0);
    packed.y = *reinterpret_cast<unsigned*>(&h1);
    *reinterpret_cast<uint2*>(g_valH + i * 4) = packed;
}

// ---------------- prepack W^T as fp16: Wt[n][k] = W[k][n] -------------------
__global__ void prepack_kernel(const float* __restrict__ W) {
    int idx = blockIdx.x * blockDim.x + threadIdx.x;
    if (idx >= KD * AGGD) return;
    int n = idx / AGGD;        // 0..127
    int k = idx % AGGD;        // 0..191
    g_Wt[idx] = __float2half_rn(W[k * KD + n]);
}

// ---------------- degree histogram (h column only) ---------------------------
__global__ void deg_kernel(const int* __restrict__ tri32) {
    int e = blockIdx.x * blockDim.x + threadIdx.x;
    if (e >= N_EDGES) return;
    int h = g_idx64 ? tri32[6 * e] : tri32[3 * e];
    atomicAdd(&g_deg[h], 1);
}

// ------- per-node score pre-reduction + att fp16 conversion ----------------
__global__ void score_pre_kernel(const float* __restrict__ ent,
                                 const float* __restrict__ att,
                                 const float* __restrict__ aw) {
    int warp = (blockIdx.x * blockDim.x + threadIdx.x) >> 5;
    int lane = threadIdx.x & 31;
    if (warp >= N_NODES) return;

    const float4* ent4 = reinterpret_cast<const float4*>(ent);
    const float4* att4 = reinterpret_cast<const float4*>(att);
    const float4* aw4  = reinterpret_cast<const float4*>(aw);

    float4 e = ent4[warp * 32 + lane];
    float4 a = att4[warp * 32 + lane];
    float4 we = __ldg(&aw4[lane]);
    float4 wa = __ldg(&aw4[32 + lane]);

    __half2 h0 = __floats2half2_rn(a.x, a.y);
    __half2 h1 = __floats2half2_rn(a.z, a.w);
    uint2 packed;
    packed.x = *reinterpret_cast<unsigned*>(&h0);
    packed.y = *reinterpret_cast<unsigned*>(&h1);
    *reinterpret_cast<uint2*>(g_attH + warp * KD + lane * 4) = packed;

    float se = e.x * we.x + e.y * we.y + e.z * we.z + e.w * we.w;
    float sa = a.x * wa.x + a.y * wa.y + a.z * wa.z + a.w * wa.w;
    #pragma unroll
    for (int o = 16; o; o >>= 1) {
        se += __shfl_xor_sync(0xFFFFFFFFu, se, o);
        sa += __shfl_xor_sync(0xFFFFFFFFu, sa, o);
    }
    if (lane == 0) {
        g_sent[warp] = se;
        g_satt[warp] = sa;
    }
}

// ---------------- 3-phase exclusive scan over degrees -----------------------
__global__ void scan_a_kernel() {
    __shared__ int sh[256];
    int t = threadIdx.x, b = blockIdx.x;
    int node = b * 256 + t;
    sh[t] = (node < N_NODES) ? g_deg[node] : 0;
    __syncthreads();
    #pragma unroll
    for (int d = 128; d; d >>= 1) {
        if (t < d) sh[t] += sh[t + d];
        __syncthreads();
    }
    if (t == 0) g_bsum[b] = sh[0];
}

__global__ void scan_b_kernel() {
    __shared__ int sh[512];
    int t = threadIdx.x;
    int v = (t < NBLK) ? g_bsum[t] : 0;
    sh[t] = v;
    __syncthreads();
    #pragma unroll
    for (int d = 1; d < 512; d <<= 1) {
        int x = (t >= d) ? sh[t - d] : 0;
        __syncthreads();
        sh[t] += x;
        __syncthreads();
    }
    if (t < NBLK) g_boff[t] = sh[t] - v;   // exclusive
}

__global__ void scan_c_kernel() {
    __shared__ int sh[256];
    int t = threadIdx.x, b = blockIdx.x;
    int node = b * 256 + t;
    int v = (node < N_NODES) ? g_deg[node] : 0;
    sh[t] = v;
    __syncthreads();
    #pragma unroll
    for (int d = 1; d < 256; d <<= 1) {
        int x = (t >= d) ? sh[t - d] : 0;
        __syncthreads();
        sh[t] += x;
        __syncthreads();
    }
    if (node < N_NODES) {
        int off = g_boff[b] + sh[t] - v;
        g_off[node] = off;
        g_cursor[node] = off;
    }
}

// ------- fused score + CSR fill: compute score, write record in place -------
__global__ void score_fill_kernel(const void* __restrict__ tri,
                                  const float* __restrict__ ab) {
    int e = blockIdx.x * blockDim.x + threadIdx.x;
    if (e >= N_EDGES) return;
    int h, a, v;
    if (g_idx64) {
        const long long* t = reinterpret_cast<const long long*>(tri) + 3LL * e;
        h = (int)t[0]; a = (int)t[1]; v = (int)t[2];
    } else {
        const int* t = reinterpret_cast<const int*>(tri) + 3 * e;
        h = t[0]; a = t[1]; v = t[2];
    }
    float s = g_sent[h] + g_satt[a] + __ldg(&ab[0]);
    s = s > 0.f ? s : 0.2f * s;                 // leaky_relu(0.2)
    float sc = __expf(s);
    atomicAdd(&g_rowsum[h], sc);
    int pos = atomicAdd(&g_cursor[h], 1);
    g_csr[pos] = make_int4(h, a, v, __float_as_int(sc));
}

// ------- gather-side weighted aggregation -> fp16 rows -----------------------
__device__ __forceinline__ void acc_edge(uint2 ua, uint2 uv, float s, int lane,
                                         float4& accA, float4& accV) {
    __half2 h0 = *reinterpret_cast<__half2*>(&ua.x);
    __half2 h1 = *reinterpret_cast<__half2*>(&ua.y);
    float2 f0 = __half22float2(h0);
    float2 f1 = __half22float2(h1);
    accA.x += f0.x * s; accA.y += f0.y * s;
    accA.z += f1.x * s; accA.w += f1.y * s;
    if (lane < 16) {
        __half2 g0 = *reinterpret_cast<__half2*>(&uv.x);
        __half2 g1 = *reinterpret_cast<__half2*>(&uv.y);
        float2 e0 = __half22float2(g0);
        float2 e1 = __half22float2(g1);
        accV.x += e0.x * s; accV.y += e0.y * s;
        accV.z += e1.x * s; accV.w += e1.y * s;
    }
}

__global__ void aggregate_kernel() {
    int warp = (blockIdx.x * blockDim.x + threadIdx.x) >> 5;
    int lane = threadIdx.x & 31;
    if (warp >= N_NODES) return;
    int beg = g_off[warp];
    int deg = g_deg[warp];

    float4 accA = make_float4(0.f, 0.f, 0.f, 0.f);
    float4 accV = make_float4(0.f, 0.f, 0.f, 0.f);

    for (int base = 0; base < deg; base += 32) {
        int4 r = make_int4(0, 0, 0, 0);
        if (base + lane < deg) r = g_csr[beg + base + lane];
        int m = min(32, deg - base);
        int i = 0;
        for (; i + 8 <= m; i += 8) {
            uint2 UA[8], UV[8];
            float S[8];
            #pragma unroll
            for (int u = 0; u < 8; u++) {
                int a = __shfl_sync(0xFFFFFFFFu, r.y, i + u);
                int v = __shfl_sync(0xFFFFFFFFu, r.z, i + u);
                S[u]  = __int_as_float(__shfl_sync(0xFFFFFFFFu, r.w, i + u));
                UA[u] = *reinterpret_cast<const uint2*>(g_attH + a * KD + lane * 4);
                UV[u] = (lane < 16)
                    ? *reinterpret_cast<const uint2*>(g_valH + v * VD + lane * 4)
                    : make_uint2(0u, 0u);
            }
            #pragma unroll
            for (int u = 0; u < 8; u++)
                acc_edge(UA[u], UV[u], S[u], lane, accA, accV);
        }
        for (; i < m; i++) {
            int a = __shfl_sync(0xFFFFFFFFu, r.y, i);
            int v = __shfl_sync(0xFFFFFFFFu, r.z, i);
            float s = __int_as_float(__shfl_sync(0xFFFFFFFFu, r.w, i));
            uint2 ua = *reinterpret_cast<const uint2*>(g_attH + a * KD + lane * 4);
            uint2 uv = (lane < 16)
                ? *reinterpret_cast<const uint2*>(g_valH + v * VD + lane * 4)
                : make_uint2(0u, 0u);
            acc_edge(ua, uv, s, lane, accA, accV);
        }
    }

    __half* dst = g_aggH + (size_t)warp * AGGD;
    __half2 a0 = __floats2half2_rn(accA.x, accA.y);
    __half2 a1 = __floats2half2_rn(accA.z, accA.w);
    uint2 pa;
    pa.x = *reinterpret_cast<unsigned*>(&a0);
    pa.y = *reinterpret_cast<unsigned*>(&a1);
    *reinterpret_cast<uint2*>(dst + lane * 4) = pa;
    if (lane < 16) {
        __half2 v0 = __floats2half2_rn(accV.x, accV.y);
        __half2 v1 = __floats2half2_rn(accV.z, accV.w);
        uint2 pv;
        pv.x = *reinterpret_cast<unsigned*>(&v0);
        pv.y = *reinterpret_cast<unsigned*>(&v1);
        *reinterpret_cast<uint2*>(dst + KD + lane * 4) = pv;
    }
}

// ======== node GEMM via wmma (HMMA): out = elu(aggH @ W / rowsum + ent) =====
// 256 threads = 8 warps; tile = 64 nodes x 128 cols; 2 CTAs/SM for overlap.
// A/W smem rows padded to 200 halves (400B == 4 mod 32 banks, conflict-free).
#define WM_THREADS 256
#define TILE_ROWS 64
#define N_TILES 1563                        // ceil(100000 / 64)
#define A_STRIDE 200                        // halves
#define D_STRIDE 132                        // floats
#define SM_A 0
#define A_BYTES (TILE_ROWS * A_STRIDE * 2)  // 25600
#define SM_W A_BYTES
#define W_BYTES (KD * A_STRIDE * 2)         // 51200
#define SM_DST (SM_W + W_BYTES)             // 76800
#define WM_SMEM_TOTAL (SM_DST + TILE_ROWS * D_STRIDE * 4)   // 110592

__global__ void __launch_bounds__(WM_THREADS, 2)
node_wmma_kernel(const float* __restrict__ ent, float* __restrict__ out) {
    extern __shared__ char smem[];
    __half* As = reinterpret_cast<__half*>(smem + SM_A);
    __half* Ws = reinterpret_cast<__half*>(smem + SM_W);
    float*  Ds = reinterpret_cast<float*>(smem + SM_DST);

    int tid = threadIdx.x;
    int wid = tid >> 5;
    int rg  = wid >> 1;     // row group 0..3
    int ch  = wid & 1;      // col half 0..1

    // Wt once per block: 128 rows x 24 uint4, padded stride 25 uint4
    for (int i = tid; i < 128 * 24; i += WM_THREADS) {
        int row = i / 24;
        int off = i % 24;
        reinterpret_cast<uint4*>(Ws + row * A_STRIDE)[off] =
            __ldg(&reinterpret_cast<const uint4*>(g_Wt)[row * 24 + off]);
    }

    const float4* ent4 = reinterpret_cast<const float4*>(ent);
    float4* out4 = reinterpret_cast<float4*>(out);

    for (int tile = blockIdx.x; tile < N_TILES; tile += gridDim.x) {
        __syncthreads();   // As/Ds safe to overwrite (prev iter consumed)
        // stage A: 64 rows x 24 uint4 (padded rows)
        for (int i = tid; i < TILE_ROWS * 24; i += WM_THREADS) {
            int row = i / 24;
            int off = i % 24;
            int node = tile * TILE_ROWS + row;
            uint4 v = make_uint4(0u, 0u, 0u, 0u);
            if (node < N_NODES)
                v = __ldg(reinterpret_cast<const uint4*>(
                        g_aggH + (size_t)node * AGGD) + off);
            reinterpret_cast<uint4*>(As + row * A_STRIDE)[off] = v;
        }
        __syncthreads();

        wmma::fragment<wmma::accumulator, 16, 16, 16, float> acc[4];
        #pragma unroll
        for (int n = 0; n < 4; n++) wmma::fill_fragment(acc[n], 0.f);

        #pragma unroll
        for (int k = 0; k < AGGD; k += 16) {
            wmma::fragment<wmma::matrix_a, 16, 16, 16, __half, wmma::row_major> a;
            wmma::load_matrix_sync(a, As + rg * 16 * A_STRIDE + k, A_STRIDE);
            #pragma unroll
            for (int n = 0; n < 4; n++) {
                wmma::fragment<wmma::matrix_b, 16, 16, 16, __half, wmma::col_major> b;
                wmma::load_matrix_sync(b, Ws + (ch * 64 + n * 16) * A_STRIDE + k,
                                       A_STRIDE);
                wmma::mma_sync(acc[n], a, b, acc[n]);
            }
        }

        #pragma unroll
        for (int n = 0; n < 4; n++)
            wmma::store_matrix_sync(Ds + rg * 16 * D_STRIDE + ch * 64 + n * 16,
                                    acc[n], D_STRIDE, wmma::mem_row_major);
        __syncthreads();

        // coalesced epilogue: 64 rows x 32 float4 = 2048 units, 8 per thread
        #pragma unroll
        for (int it = 0; it < 8; it++) {
            int idx = tid + it * WM_THREADS;   // 0..2047
            int row = idx >> 5;
            int cg  = idx & 31;
            int node = tile * TILE_ROWS + row;
            if (node < N_NODES) {
                float4 dv = *reinterpret_cast<const float4*>(
                    Ds + row * D_STRIDE + cg * 4);
                float rs = g_rowsum[node];
                float inv = rs > 0.f ? 1.f / rs : 0.f;
                float4 e = __ldg(&ent4[node * 32 + cg]);
                float t0 = dv.x * inv + e.x;
                float t1 = dv.y * inv + e.y;
                float t2 = dv.z * inv + e.z;
                float t3 = dv.w * inv + e.w;
                float4 o;
                o.x = t0 > 0.f ? t0 : expm1f(t0);   // elu, alpha=1
                o.y = t1 > 0.f ? t1 : expm1f(t1);
                o.z = t2 > 0.f ? t2 : expm1f(t2);
                o.w = t3 > 0.f ? t3 : expm1f(t3);
                out4[node * 32 + cg] = o;
            }
        }
    }
}

// ---------------- launch ----------------------------------------------------
extern "C" void kernel_launch(void* const* d_in, const int* in_sizes, int n_in,
                              void* d_out, int out_size) {
    const void*  triples = d_in[0];                       // [1e6, 3] int64/int32
    const float* ent     = (const float*)d_in[1];         // [1e5, 128]
    const float* attf    = (const float*)d_in[2];         // [1e5, 128]
    const float* valf    = (const float*)d_in[3];         // [1e5, 64]
    const float* aw      = (const float*)d_in[4];         // [256]
    const float* ab      = (const float*)d_in[5];         // [1]
    const float* W       = (const float*)d_in[6];         // [192, 128]
    float* out           = (float*)d_out;                 // [1e5, 128]

    static bool init_done = false;
    static cudaStream_t s1;
    static cudaEvent_t ev_fork, ev_join;
    if (!init_done) {
        cudaFuncSetAttribute(node_wmma_kernel,
                             cudaFuncAttributeMaxDynamicSharedMemorySize,
                             WM_SMEM_TOTAL);
        cudaStreamCreateWithFlags(&s1, cudaStreamNonBlocking);
        cudaEventCreateWithFlags(&ev_fork, cudaEventDisableTiming);
        cudaEventCreateWithFlags(&ev_join, cudaEventDisableTiming);
        init_done = true;
    }

    // fork: branch B (score_pre + prepack) is independent of branch A
    cudaEventRecord(ev_fork, 0);
    cudaStreamWaitEvent(s1, ev_fork, 0);

    // branch B (stream s1): DRAM-heavy, ~22 us
    score_pre_kernel<<<(N_NODES + 7) / 8, 256, 0, s1>>>(ent, attf, aw);
    prepack_kernel<<<(KD * AGGD + 255) / 256, 256, 0, s1>>>(W);
    cudaEventRecord(ev_join, s1);

    // branch A (default stream): sniff -> resets -> deg -> scans, ~21 us
    sniff_kernel<<<1, 256>>>((const int*)triples);
    valconv_kernel<<<(N_NODES * VD / 4 + 255) / 256, 256>>>(valf);
    deg_kernel<<<(N_EDGES + 255) / 256, 256>>>((const int*)triples);
    scan_a_kernel<<<NBLK, 256>>>();
    scan_b_kernel<<<1, 512>>>();
    scan_c_kernel<<<NBLK, 256>>>();

    // join: score_fill needs sent/satt (B) and cursors (A)
    cudaStreamWaitEvent(0, ev_join, 0);
    score_fill_kernel<<<(N_EDGES + 255) / 256, 256>>>(triples, ab);
    aggregate_kernel<<<(N_NODES * 32 + 255) / 256, 256>>>();
    node_wmma_kernel<<<296, WM_THREADS, WM_SMEM_TOTAL>>>(ent, out);
}